// round 1
// baseline (speedup 1.0000x reference)
#include <cuda_runtime.h>
#include <cuda_bf16.h>

#define NQ  4
#define NL  5
#define DIM 16

// Circuit unitary U[i][j] = <i| circuit |j>, row-major, interleaved (re, im).
__device__ float2 g_U[DIM * DIM];

// ---------------------------------------------------------------------------
// Kernel 1: build the 16x16 circuit unitary. 16 threads; thread j propagates
// basis state |j> through all 20 Rot gates + 20 CNOTs (accurate sincosf).
// ---------------------------------------------------------------------------
__global__ void build_U_kernel(const float* __restrict__ w) {
    int j = threadIdx.x;
    if (j >= DIM) return;

    float2 st[DIM];
    for (int k = 0; k < DIM; k++) st[k] = make_float2(k == j ? 1.0f : 0.0f, 0.0f);

    for (int l = 0; l < NL; l++) {
        // Rot(phi, theta, omega) on each qubit
        for (int q = 0; q < NQ; q++) {
            const float* wp = w + (l * NQ + q) * 3;
            float phi = wp[0], th = wp[1], om = wp[2];
            float sth, cth; sincosf(0.5f * th, &sth, &cth);
            float sp, cp;   sincosf(-0.5f * (phi + om), &sp, &cp);  // ep = e^{-i(phi+om)/2}
            float sm, cm;   sincosf( 0.5f * (phi - om), &sm, &cm);  // em = e^{+i(phi-om)/2}
            // U00 = ep*ct, U01 = -em*st, U10 = conj(em)*st, U11 = conj(ep)*ct
            float2 U00 = make_float2( cp * cth,  sp * cth);
            float2 U01 = make_float2(-cm * sth, -sm * sth);
            float2 U10 = make_float2( cm * sth, -sm * sth);
            float2 U11 = make_float2( cp * cth, -sp * cth);

            int stride = 8 >> q;   // qubit q lives at bit (3-q)
            for (int base = 0; base < DIM; base++) {
                if (base & stride) continue;
                float2 a = st[base];
                float2 b = st[base + stride];
                st[base] = make_float2(
                    U00.x * a.x - U00.y * a.y + U01.x * b.x - U01.y * b.y,
                    U00.x * a.y + U00.y * a.x + U01.x * b.y + U01.y * b.x);
                st[base + stride] = make_float2(
                    U10.x * a.x - U10.y * a.y + U11.x * b.x - U11.y * b.y,
                    U10.x * a.y + U10.y * a.x + U11.x * b.y + U11.y * b.x);
            }
        }
        // Entangler: CNOT(q, (q+r)%4), r = (l mod 3) + 1, applied sequentially
        int r = (l % (NQ - 1)) + 1;
        for (int q = 0; q < NQ; q++) {
            int c = q, t = (q + r) % NQ;
            int sc = 8 >> c, stt = 8 >> t;
            for (int idx = 0; idx < DIM; idx++) {
                if ((idx & sc) && !(idx & stt)) {
                    float2 tmp = st[idx];
                    st[idx] = st[idx | stt];
                    st[idx | stt] = tmp;
                }
            }
        }
    }

    for (int i = 0; i < DIM; i++) g_U[i * DIM + j] = st[i];
}

// ---------------------------------------------------------------------------
// Kernel 2: per batch element, build real product state s (16 floats),
// apply U via packed f32x2 complex MACs, square, and reduce marginals.
// ---------------------------------------------------------------------------
__global__ __launch_bounds__(256) void qmain_kernel(
    const float4* __restrict__ x, float4* __restrict__ out, int n)
{
    __shared__ ulonglong2 sU[DIM * DIM / 2];   // 2 KB: U rows, 2 complex per 16B
    {
        const unsigned long long* gU = reinterpret_cast<const unsigned long long*>(g_U);
        unsigned long long* sUf = reinterpret_cast<unsigned long long*>(sU);
        for (int k = threadIdx.x; k < DIM * DIM; k += blockDim.x) sUf[k] = gU[k];
    }
    __syncthreads();

    int b = blockIdx.x * blockDim.x + threadIdx.x;
    if (b >= n) return;

    float4 xv = x[b];
    float s0, c0, s1, c1, s2, c2, s3, c3;
    __sincosf(0.5f * xv.x, &s0, &c0);
    __sincosf(0.5f * xv.y, &s1, &c1);
    __sincosf(0.5f * xv.z, &s2, &c2);
    __sincosf(0.5f * xv.w, &s3, &c3);

    float a01[4] = {c0 * c1, c0 * s1, s0 * c1, s0 * s1};
    float a23[4] = {c2 * c3, c2 * s3, s2 * c3, s2 * s3};

    // s[j] duplicated into both f32x2 lanes
    unsigned long long sd[DIM];
#pragma unroll
    for (int p = 0; p < 4; p++) {
#pragma unroll
        for (int q = 0; q < 4; q++) {
            float v = a01[p] * a23[q];
            unsigned long long d;
            asm("mov.b64 %0, {%1, %1};" : "=l"(d) : "f"(v));
            sd[p * 4 + q] = d;
        }
    }

    float prob[DIM];
#pragma unroll
    for (int i = 0; i < DIM; i++) {
        unsigned long long acc = 0ull;   // (0.0f, 0.0f)
#pragma unroll
        for (int jj = 0; jj < 8; jj++) {
            ulonglong2 u2 = sU[i * 8 + jj];   // broadcast LDS.128: 2 complex coeffs
            asm("fma.rn.f32x2 %0, %1, %2, %0;" : "+l"(acc) : "l"(u2.x), "l"(sd[2 * jj    ]));
            asm("fma.rn.f32x2 %0, %1, %2, %0;" : "+l"(acc) : "l"(u2.y), "l"(sd[2 * jj + 1]));
        }
        float re, im;
        asm("mov.b64 {%0, %1}, %2;" : "=f"(re), "=f"(im) : "l"(acc));
        prob[i] = re * re + im * im;
    }

    float z0 = 0.f, z1 = 0.f, z2 = 0.f, z3 = 0.f;
#pragma unroll
    for (int i = 0; i < DIM; i++) {
        float pv = prob[i];
        z0 += (i & 8) ? -pv : pv;
        z1 += (i & 4) ? -pv : pv;
        z2 += (i & 2) ? -pv : pv;
        z3 += (i & 1) ? -pv : pv;
    }
    out[b] = make_float4(z0, z1, z2, z3);
}

// ---------------------------------------------------------------------------
extern "C" void kernel_launch(void* const* d_in, const int* in_sizes, int n_in,
                              void* d_out, int out_size)
{
    const float* x;
    const float* w;
    int n;
    // metadata order should be {x, weights}; disambiguate by size (weights = 60)
    if (in_sizes[0] == NL * NQ * 3) {
        w = (const float*)d_in[0];
        x = (const float*)d_in[1];
        n = in_sizes[1] / 4;
    } else {
        x = (const float*)d_in[0];
        w = (const float*)d_in[1];
        n = in_sizes[0] / 4;
    }

    build_U_kernel<<<1, DIM>>>(w);

    int threads = 256;
    int blocks = (n + threads - 1) / threads;
    qmain_kernel<<<blocks, threads>>>((const float4*)x, (float4*)d_out, n);
}